// round 11
// baseline (speedup 1.0000x reference)
#include <cuda_runtime.h>
#include <cstdint>
#include <cuda_fp16.h>
#include <mma.h>

using namespace nvcuda;

#define BB   8
#define NN   2048
#define FIN  128
#define FO   64
#define NP   96                 // g_hw row: 64 feat + 1 denom + pad (only 0..79 read)
#define ROWS_TOTAL (BB*NN)      // 16384

#define MT   64                 // m-tile rows per CTA
#define LA32 72                 // A fp32 staging stride (floats)
#define LA   72                 // A fp16 stride (halves)
#define LB   88                 // B stride (halves)
#define LC   96                 // epilogue stride (floats)
#define ASTG 3                  // A fp32 ring stages
#define BSTG 4                  // B ring stages
#define A32_FLOATS (MT*LA32)                    // 4608
#define A16_HALVES (MT*LA)                      // 4608
#define SB_HALVES  (64*LB)                      // 5632
#define SMEM_BYTES (ASTG*A32_FLOATS*4 + A16_HALVES*2 + BSTG*SB_HALVES*2) // 109568

// ---------------- scratch (device global; no allocation allowed) ------------
__device__ __align__(16) __half g_hw[ROWS_TOTAL * NP];

// ---------------- cp.async helpers ------------------------------------------
__device__ __forceinline__ void cp16(void* s, const void* g) {
    uint32_t sa = (uint32_t)__cvta_generic_to_shared(s);
    asm volatile("cp.async.cg.shared.global [%0], [%1], 16;" :: "r"(sa), "l"(g));
}
__device__ __forceinline__ void cp_commit() {
    asm volatile("cp.async.commit_group;");
}
template<int N> __device__ __forceinline__ void cp_wait() {
    asm volatile("cp.async.wait_group %0;" :: "n"(N));
}

// ============================================================================
// Kernel 1 (fused prologue): h = x@W (fp32), s2 = h@a2, g = exp(s2),
// write g_hw = fp16[g*h | g | 0]. Softmax shift-invariance: no max needed.
// ============================================================================
__global__ void __launch_bounds__(256) h_kernel(const float* __restrict__ x,
                                                const float* __restrict__ W,
                                                const float* __restrict__ a2)
{
    __shared__ float sW[FIN][FO];
    __shared__ float sX[64][36];

    const int t    = threadIdx.x;
    const int row0 = blockIdx.x * 64;

    #pragma unroll
    for (int q = 0; q < 8; q++) {
        int idx = q * 256 + t;
        ((float4*)sW)[idx] = ((const float4*)W)[idx];
    }

    const int ty = t >> 4;
    const int tx = t & 15;

    float acc[4][4];
    #pragma unroll
    for (int i = 0; i < 4; i++)
        #pragma unroll
        for (int j = 0; j < 4; j++) acc[i][j] = 0.f;

    for (int k0 = 0; k0 < FIN; k0 += 32) {
        __syncthreads();
        #pragma unroll
        for (int q = 0; q < 8; q++) {
            int idx = q * 256 + t;
            int r = idx >> 5, c = idx & 31;
            sX[r][c] = x[(size_t)(row0 + r) * FIN + k0 + c];
        }
        __syncthreads();

        #pragma unroll
        for (int c = 0; c < 32; c++) {
            float4 wv = *(const float4*)&sW[k0 + c][tx * 4];
            float xv[4];
            #pragma unroll
            for (int i = 0; i < 4; i++) xv[i] = sX[ty * 4 + i][c];
            #pragma unroll
            for (int i = 0; i < 4; i++) {
                acc[i][0] = fmaf(xv[i], wv.x, acc[i][0]);
                acc[i][1] = fmaf(xv[i], wv.y, acc[i][1]);
                acc[i][2] = fmaf(xv[i], wv.z, acc[i][2]);
                acc[i][3] = fmaf(xv[i], wv.w, acc[i][3]);
            }
        }
    }

    float a2v[4];
    #pragma unroll
    for (int j = 0; j < 4; j++) a2v[j] = __ldg(&a2[tx * 4 + j]);

    float s2p[4];
    #pragma unroll
    for (int i = 0; i < 4; i++) {
        float p = 0.f;
        #pragma unroll
        for (int j = 0; j < 4; j++) p = fmaf(acc[i][j], a2v[j], p);
        s2p[i] = p;
    }
    #pragma unroll
    for (int s = 1; s < 16; s <<= 1)
        #pragma unroll
        for (int i = 0; i < 4; i++)
            s2p[i] += __shfl_xor_sync(0xffffffffu, s2p[i], s);

    #pragma unroll
    for (int i = 0; i < 4; i++) {
        const int row = row0 + ty * 4 + i;
        const float g = expf(s2p[i]);
        __half2 h01 = __floats2half2_rn(g * acc[i][0], g * acc[i][1]);
        __half2 h23 = __floats2half2_rn(g * acc[i][2], g * acc[i][3]);
        __half2* dst = (__half2*)&g_hw[(size_t)row * NP + tx * 4];
        dst[0] = h01; dst[1] = h23;
        if (tx == 0) {
            __half2 gz = __floats2half2_rn(g, 0.f);
            uint4 q0 = make_uint4(*(const uint32_t*)&gz, 0u, 0u, 0u);
            uint4 q1 = make_uint4(0u, 0u, 0u, 0u);
            *(uint4*)&g_hw[(size_t)row * NP + 64] = q0;
            *(uint4*)&g_hw[(size_t)row * NP + 72] = q1;
        }
    }
}

// ============================================================================
// Kernel 2 (main): C = M @ g_hw via fp16 WMMA, FULLY ASYNC loads.
//  - adj: cp.async fp32 3-stage ring (3 iters of flight >> DRAM latency),
//    converted in-smem fp32->fp16 (exact for 0/1). Each thread converts the
//    exact region it cp.async'd -> no extra barrier, no WAR race on reissue.
//  - B: cp.async fp16 4-stage ring, same commit cadence (1 group/iter).
//  - No LDG in the warp path at all -> no long-scoreboard stalls, regs ~80.
// ============================================================================
__global__ void __launch_bounds__(256, 2) gat_main(const float* __restrict__ adj,
                                                   const float* __restrict__ bias,
                                                   float* __restrict__ out)
{
    extern __shared__ __align__(16) unsigned char smem_raw[];
    float*  sA32 = (float*)smem_raw;                                  // ASTG stages
    __half* sA16 = (__half*)(smem_raw + ASTG * A32_FLOATS * 4);       // 1 buffer
    __half* sB   = (__half*)(smem_raw + ASTG * A32_FLOATS * 4 + A16_HALVES * 2);

    const int t  = threadIdx.x;
    const int b  = blockIdx.x >> 5;          // 32 m-tiles per batch
    const int m0 = (blockIdx.x & 31) * MT;   // also the diag k-tile (64-aligned)

    const float*  adjB = adj  + (size_t)b * NN * NN;
    const __half* hwB  = g_hw + (size_t)b * NN * NP;

    const int w  = t >> 5;
    const int wm = w >> 1;              // 0..3 (16-row slab)
    const int wn = w & 1;               // 0: cols 0-47 (3 frags), 1: 48-79 (2)
    const int NFR = wn ? 2 : 3;

    // thread-owned A region: segments s0 = t, s1 = 256+t ; seg -> row s>>3,
    // 8 floats at col (s&7)*8. Same mapping for cp.async, LDS, STS.
    const int r0 = t >> 3,          c0 = (t & 7) * 8;
    const int r1 = (256 + t) >> 3,  c1 = c0;          // row r0+32, same col

    wmma::fragment<wmma::accumulator, 16, 16, 16, float> acc[3];
    #pragma unroll
    for (int i = 0; i < 3; i++) wmma::fill_fragment(acc[i], 0.f);

    auto issueA = [&](int tile) {
        float* dst = sA32 + (tile % ASTG) * A32_FLOATS;
        const int k0 = tile * 64;
        const float* g0 = &adjB[(size_t)(m0 + r0) * NN + k0 + c0];
        const float* g1 = &adjB[(size_t)(m0 + r1) * NN + k0 + c1];
        cp16(dst + r0 * LA32 + c0,     g0);
        cp16(dst + r0 * LA32 + c0 + 4, g0 + 4);
        cp16(dst + r1 * LA32 + c1,     g1);
        cp16(dst + r1 * LA32 + c1 + 4, g1 + 4);
    };
    auto issueB = [&](int tile) {
        __half* dst = sB + (tile & (BSTG - 1)) * SB_HALVES;
        const int k0 = tile * 64;
        #pragma unroll
        for (int q = 0; q < 3; q++) {
            int idx = q * 256 + t;
            if (idx < 640) {                       // 64 rows x 10 chunks of 16B
                int r = idx / 10, c = idx % 10;
                cp16(dst + r * LB + c * 8, hwB + (size_t)(k0 + r) * NP + c * 8);
            }
        }
    };
    auto convertA = [&](int tile) {
        const float* src = sA32 + (tile % ASTG) * A32_FLOATS;
        #pragma unroll
        for (int seg = 0; seg < 2; seg++) {
            int r = seg ? r1 : r0, c = seg ? c1 : c0;
            float4 v0 = *(const float4*)(src + r * LA32 + c);
            float4 v1 = *(const float4*)(src + r * LA32 + c + 4);
            __half2 ha = __floats2half2_rn(v0.x, v0.y);   // exact: values are 0/1
            __half2 hb = __floats2half2_rn(v0.z, v0.w);
            __half2 hc = __floats2half2_rn(v1.x, v1.y);
            __half2 hd = __floats2half2_rn(v1.z, v1.w);
            uint4 u = make_uint4(*(const uint32_t*)&ha, *(const uint32_t*)&hb,
                                 *(const uint32_t*)&hc, *(const uint32_t*)&hd);
            *(uint4*)&sA16[r * LA + c] = u;               // 16B aligned
        }
    };

    // pipeline prologue: 3 groups, each {A(i), B(i)}
    issueA(0); issueB(0); cp_commit();
    issueA(1); issueB(1); cp_commit();
    issueA(2); issueB(2); cp_commit();

    for (int it = 0; it < 32; ++it) {
        const int k0 = it * 64;

        cp_wait<2>();                 // group `it` done -> A32(it), B(it) resident
        __syncthreads();              // barrier1: also fences MMA(it-1) off sA16

        convertA(it);                 // fp32 -> fp16, self-owned regions
        if (k0 == m0) {               // diag patch (block-uniform, 1 of 32 iters)
            __syncthreads();          // order all STS before the patch
            if (t < MT) sA16[t * LA + t] = __float2half(1.f);
        }

        if (it + 3 < 32) {            // reissue into the ring (self-owned A region:
            issueA(it + 3);           //  this thread already read it above)
            issueB(it + 3);           //  B stage (it+3)&3: readers done pre-barrier1
        }
        cp_commit();                  // exactly one group per iter

        __syncthreads();              // barrier2: sA16 ready for LDSM

        const __half* b_s = sB + (it & (BSTG - 1)) * SB_HALVES;
        #pragma unroll
        for (int kk = 0; kk < 64; kk += 16) {
            wmma::fragment<wmma::matrix_a, 16, 16, 16, __half, wmma::row_major> af;
            wmma::load_matrix_sync(af, sA16 + (wm * 16) * LA + kk, LA);
            #pragma unroll
            for (int nf = 0; nf < 3; nf++) {
                if (nf < NFR) {
                    wmma::fragment<wmma::matrix_b, 16, 16, 16, __half, wmma::row_major> bf;
                    wmma::load_matrix_sync(bf, b_s + kk * LB + wn * 48 + nf * 16, LB);
                    wmma::mma_sync(acc[nf], af, bf, acc[nf]);
                }
            }
        }
    }

    // ---- epilogue: divide by denominator column (64), add bias ----
    __syncthreads();                          // last MMA done before smem reuse
    float* sC = (float*)smem_raw;             // 64 x LC floats = 24.6 KB
    #pragma unroll
    for (int nf = 0; nf < 3; nf++)
        if (nf < NFR)
            wmma::store_matrix_sync(sC + (wm * 16) * LC + wn * 48 + nf * 16,
                                    acc[nf], LC, wmma::mem_row_major);
    __syncthreads();

    const int f0 = t & 63;
    const float bi = __ldg(&bias[f0]);
    #pragma unroll
    for (int q = 0; q < 16; q++) {
        int idx = q * 256 + t;
        int r = idx >> 6;
        float den = sC[r * LC + 64];
        float val = sC[r * LC + f0] / den + bi;
        out[((size_t)b * NN + m0 + r) * FO + f0] = val;
    }
}

// ============================================================================
// launch
// ============================================================================
extern "C" void kernel_launch(void* const* d_in, const int* in_sizes, int n_in,
                              void* d_out, int out_size)
{
    const float* x    = (const float*)d_in[0];   // [8,2048,128]
    const float* adj  = (const float*)d_in[1];   // [8,2048,2048]
    const float* W    = (const float*)d_in[2];   // [128,64]
    const float* a    = (const float*)d_in[3];   // [128,1]
    const float* bias = (const float*)d_in[4];   // [64]
    float* out = (float*)d_out;

    const float* a2 = a + FO;   // s1 term cancels in the softmax

    cudaFuncSetAttribute(gat_main, cudaFuncAttributeMaxDynamicSharedMemorySize,
                         SMEM_BYTES);

    h_kernel<<<ROWS_TOTAL / 64, 256>>>(x, W, a2);
    gat_main<<<BB * (NN / MT), 256, SMEM_BYTES>>>(adj, bias, out);
}